// round 16
// baseline (speedup 1.0000x reference)
#include <cuda_runtime.h>
#include <cuda_fp16.h>
#include <cstdint>
#include <math.h>

// Problem sizes (fixed by the reference)
#define NN   8192
#define FIN  512
#define HID  256
#define OUTD 64

// ---------------------------------------------------------------------------
// Device scratch: all intermediates single fp16. Wavelets/x stay fp32
// in-place (converted to fp16 in registers after cp.async).
// All "B" operands are K-major: B^T row-major, i.e. [n][k].
// ---------------------------------------------------------------------------
__device__ __half g_W1t[(size_t)HID * FIN]; // w1^T  [256][512]
__device__ __half g_T1t[(size_t)HID * NN];  // T1^T  [256][8192]
__device__ __half g_U1t[(size_t)HID * NN];  // (f1*U1)^T [256][8192]
__device__ __half g_H  [(size_t)NN * HID];  // H row-major [8192][256]
__device__ __half g_W2t[(size_t)OUTD * HID];// w2^T  [64][256]
__device__ __half g_T2t[(size_t)OUTD * NN]; // T2^T  [64][8192]
__device__ __half g_U2t[(size_t)OUTD * NN]; // (f2*U2)^T [64][8192]

// ---------------------------------------------------------------------------
// Baseline-PTX helpers (sm_80+ features only: cp.async, ldmatrix, mma.sync)
// ---------------------------------------------------------------------------
__device__ __forceinline__ uint32_t smem_u32(const void* p) {
    uint32_t a;
    asm("{ .reg .u64 t; cvta.to.shared.u64 t, %1; cvt.u32.u64 %0, t; }"
        : "=r"(a) : "l"(p));
    return a;
}

__device__ __forceinline__ void cp_async16(uint32_t s, const void* g) {
    asm volatile("cp.async.cg.shared.global [%0], [%1], 16;"
                 :: "r"(s), "l"(g) : "memory");
}

template <int N>
__device__ __forceinline__ void cp_wait() {
    asm volatile("cp.async.wait_group %0;" :: "n"(N) : "memory");
}

__device__ __forceinline__ void ldmat4(uint32_t* r, uint32_t a) {
    asm volatile("ldmatrix.sync.aligned.m8n8.x4.shared.b16 {%0,%1,%2,%3}, [%4];"
                 : "=r"(r[0]), "=r"(r[1]), "=r"(r[2]), "=r"(r[3]) : "r"(a));
}

__device__ __forceinline__ void mma_f16(float* c, const uint32_t* a,
                                        const uint32_t* b) {
    asm volatile(
        "mma.sync.aligned.m16n8k16.row.col.f32.f16.f16.f32 "
        "{%0,%1,%2,%3}, {%4,%5,%6,%7}, {%8,%9}, {%0,%1,%2,%3};"
        : "+f"(c[0]), "+f"(c[1]), "+f"(c[2]), "+f"(c[3])
        : "r"(a[0]), "r"(a[1]), "r"(a[2]), "r"(a[3]), "r"(b[0]), "r"(b[1]));
}

// Pack two f32 into one fp16x2 register (low half = fx).
__device__ __forceinline__ uint32_t pack_h2(float fx, float fy) {
    __half2 h = __floats2half2_rn(fx, fy);
    return *reinterpret_cast<uint32_t*>(&h);
}

// fp32-A SMEM swizzle: 16B chunk permutation within the 256B row.
__device__ __forceinline__ int axmap(int r) {
    return ((r & 3) << 1) | ((r >> 2) & 1);
}

// ---------------------------------------------------------------------------
// Single-fp16 warp-MMA GEMM:
//   C[8192, Ncols] = A[8192, K] @ B[Ncols, K]^T
// APREC: 1 = A arrives fp32; converted to fp16 in registers after cp.async
//        2 = A is fp16 in global (direct ldmatrix)
// B is single fp16 (K-major).
// EPI: 0 = transposed fp16  out[n*8192 + m]
//      1 = row-major fp16   out[m*HID + n]
//      3 = fused log_softmax over the 64 cols -> fp32 outF[m*OUTD + n]
//          (requires BN == OUTD == 64 and gridDim.x == 1)
// NST-stage cp.async pipeline, one __syncthreads per k-tile.
// NTHR=128 configs run 2 CTAs/SM.
// ---------------------------------------------------------------------------
template <int BM, int BN, int WM, int WN, int NTHR, int NST, int APREC,
          int EPI, bool RELU, bool SCALE>
__global__ void __launch_bounds__(NTHR, (NTHR == 128) ? 2 : 1)
gemm_mma_kernel(const void* __restrict__ A0,   // fp32 (APREC=1) or fp16 (APREC=2)
                const __half* __restrict__ B,
                int K,
                float* __restrict__ outF,
                __half* __restrict__ oH,
                const float* __restrict__ svec)
{
    constexpr int WCOLS = BN / WN;         // warps along N
    constexpr int MT  = WM / 16;           // 16-row m tiles per warp
    constexpr int NTT = WN / 16;           // 16-col n tiles per warp
    constexpr int NT8 = WN / 8;            // 8-col n tiles per warp
    constexpr int A_BYTES = (APREC == 1) ? BM * 256 : BM * 128;
    constexpr int B_B = BN * 128;
    constexpr int STAGE = A_BYTES + B_B;
    constexpr int SMP = 65;                // fp32 softmax staging row stride

    extern __shared__ __align__(128) char smem[];
    const uint32_t sbase = smem_u32(smem);

    const int tid  = threadIdx.x;
    const int w    = tid >> 5;
    const int lane = tid & 31;
    const int wm = (w / WCOLS) * WM;
    const int wn = (w % WCOLS) * WN;
    const int m0 = blockIdx.y * BM;
    const int n0 = blockIdx.x * BN;
    const int T  = K >> 6;                 // K tiles of 64

    float acc[MT][NT8][4];
#pragma unroll
    for (int i = 0; i < MT; i++)
#pragma unroll
        for (int j = 0; j < NT8; j++)
#pragma unroll
            for (int q = 0; q < 4; q++) acc[i][j][q] = 0.0f;

    auto load_stage = [&](int s, int kt) {
        const uint32_t st = sbase + s * STAGE;
        const int kel = kt * 64;
        if (APREC == 1) {
            const float* Af = (const float*)A0;
#pragma unroll
            for (int id = tid; id < BM * 16; id += NTHR) {
                const int r = id >> 4, c = id & 15;
                const uint32_t dst = st + r * 256 + ((c ^ axmap(r)) << 4);
                cp_async16(dst, Af + (size_t)(m0 + r) * K + kel + c * 4);
            }
        } else {
            const __half* Ah = (const __half*)A0;
#pragma unroll
            for (int id = tid; id < BM * 8; id += NTHR) {
                const int r = id >> 3, c = id & 7;
                const uint32_t dst = st + r * 128 + ((c ^ (r & 7)) << 4);
                cp_async16(dst, Ah + (size_t)(m0 + r) * K + kel + c * 8);
            }
        }
#pragma unroll
        for (int id = tid; id < BN * 8; id += NTHR) {
            const int r = id >> 3, c = id & 7;
            const uint32_t dst = st + A_BYTES + r * 128 + ((c ^ (r & 7)) << 4);
            cp_async16(dst, B + (size_t)(n0 + r) * K + kel + c * 8);
        }
        asm volatile("cp.async.commit_group;" ::: "memory");
    };

    auto compute_stage = [&](int s) {
        const uint32_t aBase = sbase + s * STAGE;
        const uint32_t bBase = aBase + A_BYTES;
#pragma unroll
        for (int k16 = 0; k16 < 4; k16++) {
            uint32_t ah[MT][4];
            if (APREC == 1) {
#pragma unroll
                for (int mt = 0; mt < MT; mt++) {
                    const int rb = wm + mt * 16 + (lane >> 2);
                    const int kb = k16 * 16 + (lane & 3) * 2;
#pragma unroll
                    for (int h = 0; h < 2; h++) {        // k offset 0 / +8
#pragma unroll
                        for (int rr = 0; rr < 2; rr++) { // row offset 0 / +8
                            const int row = rb + 8 * rr;
                            const int k   = kb + 8 * h;
                            const int c   = k >> 2;
                            const uint32_t off = aBase + row * 256 +
                                ((c ^ axmap(row)) << 4) + (k & 3) * 4;
                            float2 f;
                            asm volatile("ld.shared.v2.f32 {%0,%1}, [%2];"
                                         : "=f"(f.x), "=f"(f.y) : "r"(off));
                            ah[mt][h * 2 + rr] = pack_h2(f.x, f.y);
                        }
                    }
                }
            } else {
#pragma unroll
                for (int mt = 0; mt < MT; mt++) {
                    const int r = wm + mt * 16 + (lane & 15);
                    const int c = k16 * 2 + (lane >> 4);
                    const uint32_t ad = aBase + r * 128 + ((c ^ (r & 7)) << 4);
                    ldmat4(ah[mt], ad);
                }
            }
            uint32_t bh[NTT][4];
#pragma unroll
            for (int nt = 0; nt < NTT; nt++) {
                const int r = wn + nt * 16 + ((lane >> 4) << 3) + (lane & 7);
                const int c = k16 * 2 + ((lane >> 3) & 1);
                const uint32_t bd = bBase + r * 128 + ((c ^ (r & 7)) << 4);
                ldmat4(bh[nt], bd);
            }
#pragma unroll
            for (int mt = 0; mt < MT; mt++)
#pragma unroll
                for (int n8 = 0; n8 < NT8; n8++)
                    mma_f16(acc[mt][n8], ah[mt], &bh[n8 >> 1][(n8 & 1) * 2]);
        }
    };

    // NST-stage pipeline, one barrier per k-tile.
#pragma unroll
    for (int s = 0; s < NST - 1; s++)
        if (s < T) load_stage(s, s);

    for (int kt = 0; kt < T; kt++) {
        const int rem = T - 1 - kt;
        if (rem >= NST - 2)      cp_wait<NST - 2>();
        else if (rem == 4)       cp_wait<4>();
        else if (rem == 3)       cp_wait<3>();
        else if (rem == 2)       cp_wait<2>();
        else if (rem == 1)       cp_wait<1>();
        else                     cp_wait<0>();
        __syncthreads();
        compute_stage(kt % NST);
        // Refill the stage computed LAST iteration (ordered by the barrier).
        if (kt + NST - 1 < T) load_stage((kt + NST - 1) % NST, kt + NST - 1);
    }

    if (EPI == 3) {
        // Fused log_softmax: stage fp32 accumulators in SMEM (pipeline
        // buffers are dead after this barrier), then row-reduce and write.
        __syncthreads();   // all warps finished reading pipeline stages
        float* S = reinterpret_cast<float*>(smem);
#pragma unroll
        for (int mt = 0; mt < MT; mt++) {
            const int rl = wm + mt * 16 + (lane >> 2);   // local row
#pragma unroll
            for (int n8 = 0; n8 < NT8; n8++) {
                const int nb = wn + n8 * 8 + 2 * (lane & 3);
#pragma unroll
                for (int i = 0; i < 2; i++) {
                    S[rl * SMP + nb + i]       = acc[mt][n8][i];
                    S[(rl + 8) * SMP + nb + i] = acc[mt][n8][2 + i];
                }
            }
        }
        __syncthreads();
        // 4 warps, each handles BM/4 rows; lane covers cols {lane, lane+32}.
        for (int r = w; r < BM; r += NTHR / 32) {
            float v0 = S[r * SMP + lane];
            float v1 = S[r * SMP + lane + 32];
            float m = fmaxf(v0, v1);
#pragma unroll
            for (int off = 16; off > 0; off >>= 1)
                m = fmaxf(m, __shfl_xor_sync(0xffffffffu, m, off));
            float e = expf(v0 - m) + expf(v1 - m);
#pragma unroll
            for (int off = 16; off > 0; off >>= 1)
                e += __shfl_xor_sync(0xffffffffu, e, off);
            const float lse = m + logf(e);
            float* orow = outF + (size_t)(m0 + r) * OUTD;
            orow[lane]      = v0 - lse;
            orow[lane + 32] = v1 - lse;
        }
        return;
    }

    // Standard epilogues
#pragma unroll
    for (int mt = 0; mt < MT; mt++) {
        const int mb = m0 + wm + mt * 16 + (lane >> 2);
        const float s0 = SCALE ? svec[mb]     : 1.0f;
        const float s1 = SCALE ? svec[mb + 8] : 1.0f;
#pragma unroll
        for (int n8 = 0; n8 < NT8; n8++) {
            const int nb = n0 + wn + n8 * 8 + 2 * (lane & 3);
#pragma unroll
            for (int i = 0; i < 2; i++) {
                float v0 = acc[mt][n8][i]     * s0;   // row mb,   col nb+i
                float v1 = acc[mt][n8][2 + i] * s1;   // row mb+8, col nb+i
                if (RELU) { v0 = fmaxf(v0, 0.0f); v1 = fmaxf(v1, 0.0f); }
                const int n = nb + i;
                if (EPI == 1) {
                    oH[(size_t)mb * HID + n]       = __float2half_rn(v0);
                    oH[(size_t)(mb + 8) * HID + n] = __float2half_rn(v1);
                } else {
                    oH[(size_t)n * NN + mb]     = __float2half_rn(v0);
                    oH[(size_t)n * NN + mb + 8] = __float2half_rn(v1);
                }
            }
        }
    }
}

// Both small weights, one launch: w1 [FIN,HID] -> W1t [HID,FIN],
// w2 [HID,OUTD] -> W2t [OUTD,HID], fp32 -> transposed fp16.
__global__ void conv_w_kernel(const float* __restrict__ w1,
                              __half* __restrict__ W1t,
                              const float* __restrict__ w2,
                              __half* __restrict__ W2t)
{
    const int idx = blockIdx.x * blockDim.x + threadIdx.x;
    constexpr int N1 = FIN * HID;
    constexpr int N2 = HID * OUTD;
    if (idx < N1) {
        const int r = idx / HID, c = idx % HID;
        W1t[(size_t)c * FIN + r] = __float2half_rn(w1[idx]);
    } else if (idx < N1 + N2) {
        const int j = idx - N1;
        const int r = j / OUTD, c = j % OUTD;
        W2t[(size_t)c * HID + r] = __float2half_rn(w2[j]);
    }
}

// ---------------------------------------------------------------------------
// Host side
// ---------------------------------------------------------------------------
extern "C" void kernel_launch(void* const* d_in, const int* in_sizes, int n_in,
                              void* d_out, int out_size)
{
    const float* x    = (const float*)d_in[0];
    const float* wav  = (const float*)d_in[1];
    const float* winv = (const float*)d_in[2];
    const float* w1   = (const float*)d_in[3];
    const float* f1   = (const float*)d_in[4];
    const float* w2   = (const float*)d_in[5];
    const float* f2   = (const float*)d_in[6];
    float* out = (float*)d_out;

    __half *W1t, *T1t, *U1t, *H, *W2t, *T2t, *U2t;
    cudaGetSymbolAddress((void**)&W1t, g_W1t);
    cudaGetSymbolAddress((void**)&T1t, g_T1t);
    cudaGetSymbolAddress((void**)&U1t, g_U1t);
    cudaGetSymbolAddress((void**)&H, g_H);
    cudaGetSymbolAddress((void**)&W2t, g_W2t);
    cudaGetSymbolAddress((void**)&T2t, g_T2t);
    cudaGetSymbolAddress((void**)&U2t, g_U2t);

    // --- SMEM sizes ---
    constexpr int SMEM_BIG   = 3 * (64 * 256 + 128 * 128);   // 98304
    constexpr int SMEM_SA1   = 4 * (64 * 256 + 64 * 128);    // 98304
    constexpr int SMEM_SA2   = 6 * (64 * 128 + 64 * 128);    // 98304

    cudaFuncSetAttribute((const void*)gemm_mma_kernel<64,128,32,64,128,3,1,0,false,false>,
                         cudaFuncAttributeMaxDynamicSharedMemorySize, SMEM_BIG);
    cudaFuncSetAttribute((const void*)gemm_mma_kernel<64,128,32,64,128,3,1,0,false,true>,
                         cudaFuncAttributeMaxDynamicSharedMemorySize, SMEM_BIG);
    cudaFuncSetAttribute((const void*)gemm_mma_kernel<64,128,32,64,128,3,1,1,true,false>,
                         cudaFuncAttributeMaxDynamicSharedMemorySize, SMEM_BIG);
    cudaFuncSetAttribute((const void*)gemm_mma_kernel<64,64,32,32,128,6,2,0,false,false>,
                         cudaFuncAttributeMaxDynamicSharedMemorySize, SMEM_SA2);
    cudaFuncSetAttribute((const void*)gemm_mma_kernel<64,64,32,32,128,4,1,0,false,true>,
                         cudaFuncAttributeMaxDynamicSharedMemorySize, SMEM_SA1);
    cudaFuncSetAttribute((const void*)gemm_mma_kernel<64,64,32,32,128,4,1,3,false,false>,
                         cudaFuncAttributeMaxDynamicSharedMemorySize, SMEM_SA1);

    // --- Small-weight transposed fp16 conversions (one launch) ---
    conv_w_kernel<<<(FIN * HID + HID * OUTD + 255) / 256, 256>>>(
        w1, W1t, w2, W2t);

    // --- GEMM chain ---
    // T1^T = (x @ w1)^T                      A=x fp32 [8192,512], B=w1^T
    gemm_mma_kernel<64,128,32,64,128,3,1,0,false,false>
        <<<dim3(HID/128, NN/64), 128, SMEM_BIG>>>(
            x, W1t, FIN, nullptr, T1t, nullptr);
    // (f1*U1)^T = (f1 * (winv @ T1))^T       A=winv fp32, B=T1^T
    gemm_mma_kernel<64,128,32,64,128,3,1,0,false,true>
        <<<dim3(HID/128, NN/64), 128, SMEM_BIG>>>(
            winv, T1t, NN, nullptr, U1t, f1);
    // H = relu(wav @ (f1*U1))   row-major fp16 [8192,256]
    gemm_mma_kernel<64,128,32,64,128,3,1,1,true,false>
        <<<dim3(HID/128, NN/64), 128, SMEM_BIG>>>(
            wav, U1t, NN, nullptr, H, nullptr);
    // T2^T = (H @ w2)^T                      A=H fp16 [8192,256], B=w2^T
    gemm_mma_kernel<64,64,32,32,128,6,2,0,false,false>
        <<<dim3(OUTD/64, NN/64), 128, SMEM_SA2>>>(
            H, W2t, HID, nullptr, T2t, nullptr);
    // (f2*U2)^T = (f2 * (winv @ T2))^T       A=winv fp32, B=T2^T
    gemm_mma_kernel<64,64,32,32,128,4,1,0,false,true>
        <<<dim3(OUTD/64, NN/64), 128, SMEM_SA1>>>(
            winv, T2t, NN, nullptr, U2t, f2);
    // out = log_softmax(wav @ (f2*U2))   fused epilogue, fp32 [8192,64]
    gemm_mma_kernel<64,64,32,32,128,4,1,3,false,false>
        <<<dim3(OUTD/64, NN/64), 128, SMEM_SA1>>>(
            wav, U2t, NN, out, nullptr, nullptr);
}

// round 17
// speedup vs baseline: 1.0107x; 1.0107x over previous
#include <cuda_runtime.h>
#include <cuda_fp16.h>
#include <cstdint>
#include <math.h>

// Problem sizes (fixed by the reference)
#define NN   8192
#define FIN  512
#define HID  256
#define OUTD 64

// ---------------------------------------------------------------------------
// Device scratch: all intermediates single fp16. Wavelets/x stay fp32
// in-place (converted to fp16 in registers after cp.async).
// All "B" operands are K-major: B^T row-major, i.e. [n][k].
// ---------------------------------------------------------------------------
__device__ __half g_W1t[(size_t)HID * FIN]; // w1^T  [256][512]
__device__ __half g_T1t[(size_t)HID * NN];  // T1^T  [256][8192]
__device__ __half g_U1t[(size_t)HID * NN];  // (f1*U1)^T [256][8192]
__device__ __half g_H  [(size_t)NN * HID];  // H row-major [8192][256]
__device__ __half g_W2t[(size_t)OUTD * HID];// w2^T  [64][256]
__device__ __half g_T2t[(size_t)OUTD * NN]; // T2^T  [64][8192]
__device__ __half g_U2t[(size_t)OUTD * NN]; // (f2*U2)^T [64][8192]

// ---------------------------------------------------------------------------
// Baseline-PTX helpers (sm_80+ features only: cp.async, ldmatrix, mma.sync)
// ---------------------------------------------------------------------------
__device__ __forceinline__ uint32_t smem_u32(const void* p) {
    uint32_t a;
    asm("{ .reg .u64 t; cvta.to.shared.u64 t, %1; cvt.u32.u64 %0, t; }"
        : "=r"(a) : "l"(p));
    return a;
}

__device__ __forceinline__ void cp_async16(uint32_t s, const void* g) {
    asm volatile("cp.async.cg.shared.global [%0], [%1], 16;"
                 :: "r"(s), "l"(g) : "memory");
}

template <int N>
__device__ __forceinline__ void cp_wait() {
    asm volatile("cp.async.wait_group %0;" :: "n"(N) : "memory");
}

__device__ __forceinline__ void ldmat4(uint32_t* r, uint32_t a) {
    asm volatile("ldmatrix.sync.aligned.m8n8.x4.shared.b16 {%0,%1,%2,%3}, [%4];"
                 : "=r"(r[0]), "=r"(r[1]), "=r"(r[2]), "=r"(r[3]) : "r"(a));
}

__device__ __forceinline__ void mma_f16(float* c, const uint32_t* a,
                                        const uint32_t* b) {
    asm volatile(
        "mma.sync.aligned.m16n8k16.row.col.f32.f16.f16.f32 "
        "{%0,%1,%2,%3}, {%4,%5,%6,%7}, {%8,%9}, {%0,%1,%2,%3};"
        : "+f"(c[0]), "+f"(c[1]), "+f"(c[2]), "+f"(c[3])
        : "r"(a[0]), "r"(a[1]), "r"(a[2]), "r"(a[3]), "r"(b[0]), "r"(b[1]));
}

// Pack two f32 into one fp16x2 register (low half = fx).
__device__ __forceinline__ uint32_t pack_h2(float fx, float fy) {
    __half2 h = __floats2half2_rn(fx, fy);
    return *reinterpret_cast<uint32_t*>(&h);
}

// fp32-A SMEM swizzle: 16B chunk permutation within the 256B row.
__device__ __forceinline__ int axmap(int r) {
    return ((r & 3) << 1) | ((r >> 2) & 1);
}

// ---------------------------------------------------------------------------
// Single-fp16 warp-MMA GEMM:
//   C[8192, Ncols] = A[8192, K] @ B[Ncols, K]^T
// APREC: 1 = A arrives fp32; converted to fp16 in registers after cp.async
//        2 = A is fp16 in global (direct ldmatrix)
// B is single fp16 (K-major).
// EPI: 0 = transposed fp16  out[n*8192 + m]
//      1 = row-major fp16   out[m*HID + n]
//      3 = fused log_softmax over the 64 cols -> fp32 outF[m*OUTD + n]
//          (requires BN == OUTD == 64 and gridDim.x == 1)
// NST-stage cp.async pipeline, one __syncthreads per k-tile.
// NTHR=128 configs allow 2 CTAs/SM.
// ---------------------------------------------------------------------------
template <int BM, int BN, int WM, int WN, int NTHR, int NST, int APREC,
          int EPI, bool RELU, bool SCALE>
__global__ void __launch_bounds__(NTHR, (NTHR == 128) ? 2 : 1)
gemm_mma_kernel(const void* __restrict__ A0,   // fp32 (APREC=1) or fp16 (APREC=2)
                const __half* __restrict__ B,
                int K,
                float* __restrict__ outF,
                __half* __restrict__ oH,
                const float* __restrict__ svec)
{
    constexpr int WCOLS = BN / WN;         // warps along N
    constexpr int MT  = WM / 16;           // 16-row m tiles per warp
    constexpr int NTT = WN / 16;           // 16-col n tiles per warp
    constexpr int NT8 = WN / 8;            // 8-col n tiles per warp
    constexpr int A_BYTES = (APREC == 1) ? BM * 256 : BM * 128;
    constexpr int B_B = BN * 128;
    constexpr int STAGE = A_BYTES + B_B;
    constexpr int SMP = 65;                // fp32 softmax staging row stride

    extern __shared__ __align__(128) char smem[];
    const uint32_t sbase = smem_u32(smem);

    const int tid  = threadIdx.x;
    const int w    = tid >> 5;
    const int lane = tid & 31;
    const int wm = (w / WCOLS) * WM;
    const int wn = (w % WCOLS) * WN;
    const int m0 = blockIdx.y * BM;
    const int n0 = blockIdx.x * BN;
    const int T  = K >> 6;                 // K tiles of 64

    float acc[MT][NT8][4];
#pragma unroll
    for (int i = 0; i < MT; i++)
#pragma unroll
        for (int j = 0; j < NT8; j++)
#pragma unroll
            for (int q = 0; q < 4; q++) acc[i][j][q] = 0.0f;

    auto load_stage = [&](int s, int kt) {
        const uint32_t st = sbase + s * STAGE;
        const int kel = kt * 64;
        if (APREC == 1) {
            const float* Af = (const float*)A0;
#pragma unroll
            for (int id = tid; id < BM * 16; id += NTHR) {
                const int r = id >> 4, c = id & 15;
                const uint32_t dst = st + r * 256 + ((c ^ axmap(r)) << 4);
                cp_async16(dst, Af + (size_t)(m0 + r) * K + kel + c * 4);
            }
        } else {
            const __half* Ah = (const __half*)A0;
#pragma unroll
            for (int id = tid; id < BM * 8; id += NTHR) {
                const int r = id >> 3, c = id & 7;
                const uint32_t dst = st + r * 128 + ((c ^ (r & 7)) << 4);
                cp_async16(dst, Ah + (size_t)(m0 + r) * K + kel + c * 8);
            }
        }
#pragma unroll
        for (int id = tid; id < BN * 8; id += NTHR) {
            const int r = id >> 3, c = id & 7;
            const uint32_t dst = st + A_BYTES + r * 128 + ((c ^ (r & 7)) << 4);
            cp_async16(dst, B + (size_t)(n0 + r) * K + kel + c * 8);
        }
        asm volatile("cp.async.commit_group;" ::: "memory");
    };

    auto compute_stage = [&](int s) {
        const uint32_t aBase = sbase + s * STAGE;
        const uint32_t bBase = aBase + A_BYTES;
#pragma unroll
        for (int k16 = 0; k16 < 4; k16++) {
            uint32_t ah[MT][4];
            if (APREC == 1) {
#pragma unroll
                for (int mt = 0; mt < MT; mt++) {
                    const int rb = wm + mt * 16 + (lane >> 2);
                    const int kb = k16 * 16 + (lane & 3) * 2;
#pragma unroll
                    for (int h = 0; h < 2; h++) {        // k offset 0 / +8
#pragma unroll
                        for (int rr = 0; rr < 2; rr++) { // row offset 0 / +8
                            const int row = rb + 8 * rr;
                            const int k   = kb + 8 * h;
                            const int c   = k >> 2;
                            const uint32_t off = aBase + row * 256 +
                                ((c ^ axmap(row)) << 4) + (k & 3) * 4;
                            float2 f;
                            asm volatile("ld.shared.v2.f32 {%0,%1}, [%2];"
                                         : "=f"(f.x), "=f"(f.y) : "r"(off));
                            ah[mt][h * 2 + rr] = pack_h2(f.x, f.y);
                        }
                    }
                }
            } else {
#pragma unroll
                for (int mt = 0; mt < MT; mt++) {
                    const int r = wm + mt * 16 + (lane & 15);
                    const int c = k16 * 2 + (lane >> 4);
                    const uint32_t ad = aBase + r * 128 + ((c ^ (r & 7)) << 4);
                    ldmat4(ah[mt], ad);
                }
            }
            uint32_t bh[NTT][4];
#pragma unroll
            for (int nt = 0; nt < NTT; nt++) {
                const int r = wn + nt * 16 + ((lane >> 4) << 3) + (lane & 7);
                const int c = k16 * 2 + ((lane >> 3) & 1);
                const uint32_t bd = bBase + r * 128 + ((c ^ (r & 7)) << 4);
                ldmat4(bh[nt], bd);
            }
#pragma unroll
            for (int mt = 0; mt < MT; mt++)
#pragma unroll
                for (int n8 = 0; n8 < NT8; n8++)
                    mma_f16(acc[mt][n8], ah[mt], &bh[n8 >> 1][(n8 & 1) * 2]);
        }
    };

    // NST-stage pipeline, one barrier per k-tile.
#pragma unroll
    for (int s = 0; s < NST - 1; s++)
        if (s < T) load_stage(s, s);

    for (int kt = 0; kt < T; kt++) {
        const int rem = T - 1 - kt;
        if (rem >= NST - 2)      cp_wait<NST - 2>();
        else if (rem == 4)       cp_wait<4>();
        else if (rem == 3)       cp_wait<3>();
        else if (rem == 2)       cp_wait<2>();
        else if (rem == 1)       cp_wait<1>();
        else                     cp_wait<0>();
        __syncthreads();
        compute_stage(kt % NST);
        // Refill the stage computed LAST iteration (ordered by the barrier).
        if (kt + NST - 1 < T) load_stage((kt + NST - 1) % NST, kt + NST - 1);
    }

    if (EPI == 3) {
        // Fused log_softmax: stage fp32 accumulators in SMEM (pipeline
        // buffers are dead after this barrier), then row-reduce and write.
        __syncthreads();   // all warps finished reading pipeline stages
        float* S = reinterpret_cast<float*>(smem);
#pragma unroll
        for (int mt = 0; mt < MT; mt++) {
            const int rl = wm + mt * 16 + (lane >> 2);   // local row
#pragma unroll
            for (int n8 = 0; n8 < NT8; n8++) {
                const int nb = wn + n8 * 8 + 2 * (lane & 3);
#pragma unroll
                for (int i = 0; i < 2; i++) {
                    S[rl * SMP + nb + i]       = acc[mt][n8][i];
                    S[(rl + 8) * SMP + nb + i] = acc[mt][n8][2 + i];
                }
            }
        }
        __syncthreads();
        // 4 warps; lane covers cols {lane, lane+32}.
        for (int r = w; r < BM; r += NTHR / 32) {
            float v0 = S[r * SMP + lane];
            float v1 = S[r * SMP + lane + 32];
            float m = fmaxf(v0, v1);
#pragma unroll
            for (int off = 16; off > 0; off >>= 1)
                m = fmaxf(m, __shfl_xor_sync(0xffffffffu, m, off));
            float e = expf(v0 - m) + expf(v1 - m);
#pragma unroll
            for (int off = 16; off > 0; off >>= 1)
                e += __shfl_xor_sync(0xffffffffu, e, off);
            const float lse = m + logf(e);
            float* orow = outF + (size_t)(m0 + r) * OUTD;
            orow[lane]      = v0 - lse;
            orow[lane + 32] = v1 - lse;
        }
        return;
    }

    // Standard epilogues
#pragma unroll
    for (int mt = 0; mt < MT; mt++) {
        const int mb = m0 + wm + mt * 16 + (lane >> 2);
        const float s0 = SCALE ? svec[mb]     : 1.0f;
        const float s1 = SCALE ? svec[mb + 8] : 1.0f;
#pragma unroll
        for (int n8 = 0; n8 < NT8; n8++) {
            const int nb = n0 + wn + n8 * 8 + 2 * (lane & 3);
#pragma unroll
            for (int i = 0; i < 2; i++) {
                float v0 = acc[mt][n8][i]     * s0;   // row mb,   col nb+i
                float v1 = acc[mt][n8][2 + i] * s1;   // row mb+8, col nb+i
                if (RELU) { v0 = fmaxf(v0, 0.0f); v1 = fmaxf(v1, 0.0f); }
                const int n = nb + i;
                if (EPI == 1) {
                    oH[(size_t)mb * HID + n]       = __float2half_rn(v0);
                    oH[(size_t)(mb + 8) * HID + n] = __float2half_rn(v1);
                } else {
                    oH[(size_t)n * NN + mb]     = __float2half_rn(v0);
                    oH[(size_t)n * NN + mb + 8] = __float2half_rn(v1);
                }
            }
        }
    }
}

// Both small weights, one launch: w1 [FIN,HID] -> W1t [HID,FIN],
// w2 [HID,OUTD] -> W2t [OUTD,HID], fp32 -> transposed fp16.
__global__ void conv_w_kernel(const float* __restrict__ w1,
                              __half* __restrict__ W1t,
                              const float* __restrict__ w2,
                              __half* __restrict__ W2t)
{
    const int idx = blockIdx.x * blockDim.x + threadIdx.x;
    constexpr int N1 = FIN * HID;
    constexpr int N2 = HID * OUTD;
    if (idx < N1) {
        const int r = idx / HID, c = idx % HID;
        W1t[(size_t)c * FIN + r] = __float2half_rn(w1[idx]);
    } else if (idx < N1 + N2) {
        const int j = idx - N1;
        const int r = j / OUTD, c = j % OUTD;
        W2t[(size_t)c * HID + r] = __float2half_rn(w2[j]);
    }
}

// ---------------------------------------------------------------------------
// Host side
// ---------------------------------------------------------------------------
extern "C" void kernel_launch(void* const* d_in, const int* in_sizes, int n_in,
                              void* d_out, int out_size)
{
    const float* x    = (const float*)d_in[0];
    const float* wav  = (const float*)d_in[1];
    const float* winv = (const float*)d_in[2];
    const float* w1   = (const float*)d_in[3];
    const float* f1   = (const float*)d_in[4];
    const float* w2   = (const float*)d_in[5];
    const float* f2   = (const float*)d_in[6];
    float* out = (float*)d_out;

    __half *W1t, *T1t, *U1t, *H, *W2t, *T2t, *U2t;
    cudaGetSymbolAddress((void**)&W1t, g_W1t);
    cudaGetSymbolAddress((void**)&T1t, g_T1t);
    cudaGetSymbolAddress((void**)&U1t, g_U1t);
    cudaGetSymbolAddress((void**)&H, g_H);
    cudaGetSymbolAddress((void**)&W2t, g_W2t);
    cudaGetSymbolAddress((void**)&T2t, g_T2t);
    cudaGetSymbolAddress((void**)&U2t, g_U2t);

    // --- SMEM sizes ---
    // big:  3 stages x (64*256 + 128*128) = 98304 (2 CTAs/SM -> 192KB)
    // sm1:  6 stages x (32*256 +  64*128) = 98304 (2 CTAs/SM)
    // sm2:  6 stages x (32*128 +  64*128) = 73728 (2 CTAs/SM)
    constexpr int SMEM_BIG = 3 * (64 * 256 + 128 * 128);
    constexpr int SMEM_SA1 = 6 * (32 * 256 + 64 * 128);
    constexpr int SMEM_SA2 = 6 * (32 * 128 + 64 * 128);

    cudaFuncSetAttribute((const void*)gemm_mma_kernel<64,128,32,64,128,3,1,0,false,false>,
                         cudaFuncAttributeMaxDynamicSharedMemorySize, SMEM_BIG);
    cudaFuncSetAttribute((const void*)gemm_mma_kernel<64,128,32,64,128,3,1,0,false,true>,
                         cudaFuncAttributeMaxDynamicSharedMemorySize, SMEM_BIG);
    cudaFuncSetAttribute((const void*)gemm_mma_kernel<64,128,32,64,128,3,1,1,true,false>,
                         cudaFuncAttributeMaxDynamicSharedMemorySize, SMEM_BIG);
    cudaFuncSetAttribute((const void*)gemm_mma_kernel<32,64,16,32,128,6,2,0,false,false>,
                         cudaFuncAttributeMaxDynamicSharedMemorySize, SMEM_SA2);
    cudaFuncSetAttribute((const void*)gemm_mma_kernel<32,64,16,32,128,6,1,0,false,true>,
                         cudaFuncAttributeMaxDynamicSharedMemorySize, SMEM_SA1);
    cudaFuncSetAttribute((const void*)gemm_mma_kernel<32,64,16,32,128,6,1,3,false,false>,
                         cudaFuncAttributeMaxDynamicSharedMemorySize, SMEM_SA1);

    // --- Small-weight transposed fp16 conversions (one launch) ---
    conv_w_kernel<<<(FIN * HID + HID * OUTD + 255) / 256, 256>>>(
        w1, W1t, w2, W2t);

    // --- GEMM chain (big GEMMs identical to the best config) ---
    // T1^T = (x @ w1)^T                      A=x fp32 [8192,512], B=w1^T
    gemm_mma_kernel<64,128,32,64,128,3,1,0,false,false>
        <<<dim3(HID/128, NN/64), 128, SMEM_BIG>>>(
            x, W1t, FIN, nullptr, T1t, nullptr);
    // (f1*U1)^T = (f1 * (winv @ T1))^T       A=winv fp32, B=T1^T
    gemm_mma_kernel<64,128,32,64,128,3,1,0,false,true>
        <<<dim3(HID/128, NN/64), 128, SMEM_BIG>>>(
            winv, T1t, NN, nullptr, U1t, f1);
    // H = relu(wav @ (f1*U1))   row-major fp16 [8192,256]
    gemm_mma_kernel<64,128,32,64,128,3,1,1,true,false>
        <<<dim3(HID/128, NN/64), 128, SMEM_BIG>>>(
            wav, U1t, NN, nullptr, H, nullptr);
    // T2^T = (H @ w2)^T                      A=H fp16, BM=32 -> grid 256
    gemm_mma_kernel<32,64,16,32,128,6,2,0,false,false>
        <<<dim3(OUTD/64, NN/32), 128, SMEM_SA2>>>(
            H, W2t, HID, nullptr, T2t, nullptr);
    // (f2*U2)^T = (f2 * (winv @ T2))^T       A=winv fp32, BM=32 -> grid 256
    gemm_mma_kernel<32,64,16,32,128,6,1,0,false,true>
        <<<dim3(OUTD/64, NN/32), 128, SMEM_SA1>>>(
            winv, T2t, NN, nullptr, U2t, f2);
    // out = log_softmax(wav @ (f2*U2))       fused epilogue, BM=32
    gemm_mma_kernel<32,64,16,32,128,6,1,3,false,false>
        <<<dim3(OUTD/64, NN/32), 128, SMEM_SA1>>>(
            wav, U2t, NN, out, nullptr, nullptr);
}